// round 15
// baseline (speedup 1.0000x reference)
#include <cuda_runtime.h>

typedef unsigned int u32;

// Problem constants (fixed by the dataset)
#define B_  16
#define H_  12
#define N_  576
#define D_  64
#define C_  768
#define GW_ 24

// ---- scratch ----
__device__ float g_Q [B_*H_*N_*D_];
__device__ float g_K [B_*H_*N_*D_];
__device__ float g_V [B_*H_*N_*D_];
__device__ float g_AO[B_*N_*C_];
__device__ float g_SP[H_*N_*N_];      // positional softmax table (L2-resident, 15.9MB)

// ---------------------------------------------------------------------------
// TF32 helpers
// ---------------------------------------------------------------------------
__device__ __forceinline__ u32 f2tf(float f) {
    u32 u;
    asm("cvt.rna.tf32.f32 %0, %1;" : "=r"(u) : "f"(f));
    return u;
}
// Fragment mapping (m16n8k8, verified):
//   A: a0=(m=g,k=tq) a1=(m=g+8,k=tq) a2=(m=g,k=tq+4) a3=(m=g+8,k=tq+4)
//   B: b0=(k=tq,n=g) b1=(k=tq+4,n=g)
//   C: c0=(m=g,n=2tq) c1=(g,2tq+1) c2=(g+8,2tq) c3=(g+8,2tq+1)
__device__ __forceinline__ void mma_tf32(float* d, const u32* a, const u32* b) {
    asm volatile(
        "mma.sync.aligned.m16n8k8.row.col.f32.tf32.tf32.f32 "
        "{%0,%1,%2,%3}, {%4,%5,%6,%7}, {%8,%9}, {%0,%1,%2,%3};"
        : "+f"(d[0]), "+f"(d[1]), "+f"(d[2]), "+f"(d[3])
        : "r"(a[0]), "r"(a[1]), "r"(a[2]), "r"(a[3]), "r"(b[0]), "r"(b[1]));
}

__device__ __forceinline__ uint4 f2tf4(float4 v) {
    uint4 u; u.x = f2tf(v.x); u.y = f2tf(v.y); u.z = f2tf(v.z); u.w = f2tf(v.w);
    return u;
}

#define CP16(saddr, gptr) \
    asm volatile("cp.async.cg.shared.global [%0], [%1], 16;\n" \
                 :: "r"(saddr), "l"(gptr))
#define CP_COMMIT() asm volatile("cp.async.commit_group;\n")
#define CP_WAIT2()  asm volatile("cp.async.wait_group 2;\n")

// ===========================================================================
// TF32 GEMM core: 128x128 tile, BK=16, 8 warps x (64x32) warp tiles,
// 256 threads -> 16 warps/SM at 2 blocks (4/SMSP: latency hiding).
// 4-stage cp.async pipeline; tf32 CVT on the fragment-load path (same
// cvt.rna as before -> bit-identical numerics).
// Crossbar budget: 8 warps x 6KB = 48KB/iter = 384 cyc < 512 tensor cyc.
// Conflict-free fragment banking:
//   sA [m=128][SA_ST=20]: banks (20g+tq)%32 -> 32 distinct.
//   sB [k=16][SB_ST=136]: banks (8tq+g)%32  -> 32 distinct.
// ===========================================================================
#define SA_ST 20
#define SB_ST 136
#define A_WORDS_ (128 * SA_ST)               // 2560
#define STAGE_WORDS (A_WORDS_ + 16 * SB_ST)  // 4736
#define NSTG 4
#define GEMM_SMEM_BYTES (NSTG * STAGE_WORDS * 4)   // 75776

#define EPI_QKV  0
#define EPI_PROJ 1

template<int EPI>
__device__ __forceinline__ void gemm_tf32_body(
    const float* __restrict__ A, const float* __restrict__ Wm,
    int row0, int col0,
    float* __restrict__ dst, const float* __restrict__ bias)
{
    extern __shared__ __align__(16) float dynsmf[];

    const int t    = threadIdx.x;        // 0..255
    const int w    = t >> 5;             // 0..7
    const int lane = t & 31;
    const int g    = lane >> 2;
    const int tq   = lane & 3;
    const int m0w  = (w & 1) * 64;       // 0 / 64
    const int n0w  = (w >> 1) * 32;      // 0,32,64,96

    // loaders (256 threads): A 128x16 = 512 float4 (2/thread),
    //                        B 16x128 = 512 float4 (2/thread)
    const int ar = t >> 2;               // A rows ar, ar+64
    const int ak = (t & 3) * 4;
    const int bk = t >> 5;               // B k-rows bk, bk+8
    const int bn = (t & 31) * 4;

    const u32 sbase = (u32)__cvta_generic_to_shared(dynsmf);

    const float* gAr = &A [(row0 + ar) * C_ + ak];
    const float* gBr = &Wm[(bk) * C_ + col0 + bn];
    const u32 aOff = (ar * SA_ST + ak) * 4;
    const u32 bOff = (A_WORDS_ + bk * SB_ST + bn) * 4;

#define ISSUE_TILE(kt, stg) do {                                        \
        const float* gA = gAr + (kt) * 16;                              \
        const float* gB = gBr + (size_t)(kt) * 16 * C_;                 \
        u32 aA = sbase + (u32)(stg) * (STAGE_WORDS * 4) + aOff;         \
        u32 bA = sbase + (u32)(stg) * (STAGE_WORDS * 4) + bOff;         \
        CP16(aA,              gA);                                      \
        CP16(aA + 64*SA_ST*4, gA + 64*C_);                              \
        CP16(bA,              gB);                                      \
        CP16(bA + 8*SB_ST*4,  gB + 8*C_);                               \
        CP_COMMIT();                                                    \
    } while (0)

    float acc[4][4][4] = {};

    // prologue: 3 tiles in flight
    ISSUE_TILE(0, 0);
    ISSUE_TILE(1, 1);
    ISSUE_TILE(2, 2);

    const int NIT = C_ / 16;             // 48
    for (int it = 0; it < NIT; it++) {
        CP_WAIT2();                      // tile 'it' resident
        __syncthreads();                 // visible to all; prev-iter MMAs done
        if (it + 3 < NIT)
            ISSUE_TILE(it + 3, (it + 3) & (NSTG - 1));

        const float* sAf = dynsmf + (it & (NSTG - 1)) * STAGE_WORDS;
        const float* sBf = sAf + A_WORDS_;

        #pragma unroll
        for (int ks = 0; ks < 16; ks += 8) {
            u32 af[4][4], bf[4][2];
            #pragma unroll
            for (int mb = 0; mb < 4; mb++) {
                int mrow = m0w + mb * 16 + g;
                af[mb][0] = f2tf(sAf[(mrow    ) * SA_ST + ks + tq    ]);
                af[mb][1] = f2tf(sAf[(mrow + 8) * SA_ST + ks + tq    ]);
                af[mb][2] = f2tf(sAf[(mrow    ) * SA_ST + ks + tq + 4]);
                af[mb][3] = f2tf(sAf[(mrow + 8) * SA_ST + ks + tq + 4]);
            }
            #pragma unroll
            for (int nb = 0; nb < 4; nb++) {
                int nc = n0w + nb * 8 + g;
                bf[nb][0] = f2tf(sBf[(ks + tq    ) * SB_ST + nc]);
                bf[nb][1] = f2tf(sBf[(ks + tq + 4) * SB_ST + nc]);
            }
            #pragma unroll
            for (int mb = 0; mb < 4; mb++)
                #pragma unroll
                for (int nb = 0; nb < 4; nb++)
                    mma_tf32(acc[mb][nb], af[mb], bf[nb]);
        }
    }
#undef ISSUE_TILE

    // epilogue: float2 stores (cols 2tq, 2tq+1 adjacent)
    #pragma unroll
    for (int mb = 0; mb < 4; mb++) {
        int r0 = row0 + m0w + mb * 16 + g;
        #pragma unroll
        for (int nb = 0; nb < 4; nb++) {
            int c0 = col0 + n0w + nb * 8 + 2 * tq;
            #pragma unroll
            for (int rr = 0; rr < 2; rr++) {
                int row = r0 + rr * 8;
                float2 v;
                v.x = acc[mb][nb][rr * 2 + 0];
                v.y = acc[mb][nb][rr * 2 + 1];
                if (EPI == EPI_QKV) {
                    int b  = row / N_;
                    int n  = row - b * N_;
                    int hh = c0 >> 6;
                    int dd = c0 & 63;
                    *(float2*)&dst[(((b * H_ + hh) * N_) + n) * D_ + dd] = v;
                } else {
                    v.x += bias[c0];
                    v.y += bias[c0 + 1];
                    *(float2*)&dst[(size_t)row * C_ + c0] = v;
                }
            }
        }
    }
}

__global__ __launch_bounds__(256, 2) void qkv_mma_kernel(
    const float* __restrict__ x,
    const float* __restrict__ Wq,
    const float* __restrict__ Wk,
    const float* __restrict__ Wv)
{
    const float* W   = (blockIdx.z == 0) ? Wq : (blockIdx.z == 1) ? Wk : Wv;
    float*       dst = (blockIdx.z == 0) ? g_Q : (blockIdx.z == 1) ? g_K : g_V;
    gemm_tf32_body<EPI_QKV>(x, W, blockIdx.x * 128, blockIdx.y * 128, dst, 0);
}

__global__ __launch_bounds__(256, 2) void proj_mma_kernel(
    const float* __restrict__ Wproj,
    const float* __restrict__ bproj,
    float* __restrict__ out)
{
    gemm_tf32_body<EPI_PROJ>(g_AO, Wproj, blockIdx.x * 128, blockIdx.y * 128,
                             out, bproj);
}

// ===========================================================================
// K2: positional softmax table S_pos[h][n][m]. One warp per (h,n) row.
// ===========================================================================
__global__ __launch_bounds__(256) void pos_kernel(
    const float* __restrict__ pos_w,
    const float* __restrict__ pos_b)
{
    const int warp = threadIdx.x >> 5;
    const int lane = threadIdx.x & 31;
    const int row  = blockIdx.x * 8 + warp;
    const int h    = row / N_;
    const int n    = row - h * N_;

    const float wx = pos_w[0 * H_ + h];
    const float wy = pos_w[1 * H_ + h];
    const float wz = pos_w[2 * H_ + h];
    const float pb = pos_b[h];
    const int nx = n % GW_, ny = n / GW_;

    float buf[18];
    float mx = -1e30f;
    #pragma unroll
    for (int i = 0; i < 18; i++) {
        int m  = lane + 32 * i;
        float fdx = (float)((m % GW_) - nx);
        float fdy = (float)((m / GW_) - ny);
        float s = wx * fdx + wy * fdy + wz * (fdx * fdx + fdy * fdy) + pb;
        buf[i] = s;
        mx = fmaxf(mx, s);
    }
    #pragma unroll
    for (int o = 16; o; o >>= 1) mx = fmaxf(mx, __shfl_xor_sync(0xffffffffu, mx, o));

    float sum = 0.f;
    #pragma unroll
    for (int i = 0; i < 18; i++) { buf[i] = __expf(buf[i] - mx); sum += buf[i]; }
    #pragma unroll
    for (int o = 16; o; o >>= 1) sum += __shfl_xor_sync(0xffffffffu, sum, o);

    const float inv = 1.f / sum;
    float* dstp = g_SP + (size_t)row * N_;
    #pragma unroll
    for (int i = 0; i < 18; i++) dstp[lane + 32 * i] = buf[i] * inv;
}

// ===========================================================================
// K3: fused attention, TF32 MMA, 64 query rows per block (512 threads).
// (R12 structure — proven fastest; the R13 phase-A double-buffer regressed.)
// ===========================================================================
#define SQ_ST 68
#define SK_ST 68
#define SV_ST 72
#define SS_ST 580
#define AROWS 64
#define ATHREADS 512
#define ATTN_SMEM_WORDS (AROWS*SQ_ST + AROWS*SV_ST + AROWS*SS_ST)

__global__ __launch_bounds__(ATHREADS, 1) void attn_kernel(const float* __restrict__ gating)
{
    extern __shared__ __align__(16) u32 smw[];
    u32*   sQ   = smw;                           // tf32 [64][SQ_ST]
    u32*   sKV  = sQ + AROWS * SQ_ST;            // tf32 K [64][SK_ST] / V [64][SV_ST]
    float* sS   = (float*)(sKV + AROWS * SV_ST); // fp32 scores -> tf32 weights [64][SS_ST]
    u32*   sSw  = (u32*)sS;

    const int b  = blockIdx.z;
    const int h  = blockIdx.y;
    const int n0 = blockIdx.x * AROWS;
    const int t  = threadIdx.x;
    const int w    = t >> 5;
    const int lane = t & 31;
    const int g    = lane >> 2;
    const int tq   = lane & 3;
    const int roff = (w & 3) * 16;     // row group: 0,16,32,48
    const int cg   = (w >> 2) * 16;    // col group within 64

    const float* Qp = g_Q + (((size_t)(b * H_ + h)) * N_ + n0) * D_;
    const float* Kp = g_K + ((size_t)(b * H_ + h)) * N_ * D_;
    const float* Vp = g_V + ((size_t)(b * H_ + h)) * N_ * D_;

    const int lr0 = t >> 4;            // rows lr0, lr0+32
    const int ld4 = (t & 15) << 2;

    *(uint4*)&sQ[(lr0     ) * SQ_ST + ld4] = f2tf4(*(const float4*)&Qp[(lr0     ) * D_ + ld4]);
    *(uint4*)&sQ[(lr0 + 32) * SQ_ST + ld4] = f2tf4(*(const float4*)&Qp[(lr0 + 32) * D_ + ld4]);
    __syncthreads();

    u32 qf[8][4];
    #pragma unroll
    for (int ks = 0; ks < 8; ks++) {
        int k0 = ks * 8;
        qf[ks][0] = sQ[(roff + g    ) * SQ_ST + k0 + tq    ];
        qf[ks][1] = sQ[(roff + g + 8) * SQ_ST + k0 + tq    ];
        qf[ks][2] = sQ[(roff + g    ) * SQ_ST + k0 + tq + 4];
        qf[ks][3] = sQ[(roff + g + 8) * SQ_ST + k0 + tq + 4];
    }

    // ---------------- Phase A: scores via MMA (prefetched K tiles) ---------
    float4 pre0 = *(const float4*)&Kp[(lr0     ) * D_ + ld4];
    float4 pre1 = *(const float4*)&Kp[(lr0 + 32) * D_ + ld4];

    for (int tile = 0; tile < 9; tile++) {
        const int m0 = tile * 64;
        __syncthreads();
        *(uint4*)&sKV[(lr0     ) * SK_ST + ld4] = f2tf4(pre0);
        *(uint4*)&sKV[(lr0 + 32) * SK_ST + ld4] = f2tf4(pre1);
        if (tile < 8) {
            const float* Kn = Kp + (m0 + 64) * D_;
            pre0 = *(const float4*)&Kn[(lr0     ) * D_ + ld4];
            pre1 = *(const float4*)&Kn[(lr0 + 32) * D_ + ld4];
        }
        __syncthreads();

        float acc[2][4] = {};
        #pragma unroll
        for (int ks = 0; ks < 8; ks++) {
            int k0 = ks * 8;
            #pragma unroll
            for (int nt = 0; nt < 2; nt++) {
                int nb = cg + nt * 8;
                u32 bfr[2];
                bfr[0] = sKV[(nb + g) * SK_ST + k0 + tq    ];
                bfr[1] = sKV[(nb + g) * SK_ST + k0 + tq + 4];
                mma_tf32(acc[nt], qf[ks], bfr);
            }
        }
        #pragma unroll
        for (int nt = 0; nt < 2; nt++) {
            int c0 = m0 + cg + nt * 8 + 2 * tq;
            float2 v0; v0.x = acc[nt][0] * 0.125f; v0.y = acc[nt][1] * 0.125f;
            float2 v1; v1.x = acc[nt][2] * 0.125f; v1.y = acc[nt][3] * 0.125f;
            *(float2*)&sS[(roff + g    ) * SS_ST + c0] = v0;
            *(float2*)&sS[(roff + g + 8) * SS_ST + c0] = v1;
        }
    }

    pre0 = *(const float4*)&Vp[(lr0     ) * D_ + ld4];
    pre1 = *(const float4*)&Vp[(lr0 + 32) * D_ + ld4];

    __syncthreads();

    // ---------------- Merged softmax + positional blend (tf32 out) ---------
    {
        const float gt = 1.f / (1.f + __expf(-gating[h]));
        const float c1 = 1.f - gt;
        const bool  tail = (lane < 16);

        for (int r = w; r < AROWS; r += 16) {
            float4* rowp4 = (float4*)(sS + r * SS_ST);
            uint4*  rowp4u = (uint4*)rowp4;
            float4 e4[5];
            float mx = -1e30f;
            #pragma unroll
            for (int i = 0; i < 4; i++) {
                e4[i] = rowp4[lane + 32 * i];
                mx = fmaxf(mx, fmaxf(fmaxf(e4[i].x, e4[i].y), fmaxf(e4[i].z, e4[i].w)));
            }
            if (tail) {
                e4[4] = rowp4[128 + lane];
                mx = fmaxf(mx, fmaxf(fmaxf(e4[4].x, e4[4].y), fmaxf(e4[4].z, e4[4].w)));
            } else {
                e4[4].x = e4[4].y = e4[4].z = e4[4].w = -1e30f;
            }
            #pragma unroll
            for (int o = 16; o; o >>= 1) mx = fmaxf(mx, __shfl_xor_sync(0xffffffffu, mx, o));

            float sum = 0.f;
            #pragma unroll
            for (int i = 0; i < 5; i++) {
                e4[i].x = __expf(e4[i].x - mx);
                e4[i].y = __expf(e4[i].y - mx);
                e4[i].z = __expf(e4[i].z - mx);
                e4[i].w = __expf(e4[i].w - mx);
                sum += (e4[i].x + e4[i].y) + (e4[i].z + e4[i].w);
            }
            #pragma unroll
            for (int o = 16; o; o >>= 1) sum += __shfl_xor_sync(0xffffffffu, sum, o);
            const float a = c1 / sum;

            const float4* sp4 = (const float4*)(g_SP + ((size_t)h * N_ + n0 + r) * N_);
            #pragma unroll
            for (int i = 0; i < 4; i++) {
                float4 s = sp4[lane + 32 * i];
                uint4 o4;
                o4.x = f2tf(a * e4[i].x + gt * s.x);
                o4.y = f2tf(a * e4[i].y + gt * s.y);
                o4.z = f2tf(a * e4[i].z + gt * s.z);
                o4.w = f2tf(a * e4[i].w + gt * s.w);
                rowp4u[lane + 32 * i] = o4;
            }
            if (tail) {
                float4 s = sp4[128 + lane];
                uint4 o4;
                o4.x = f2tf(a * e4[4].x + gt * s.x);
                o4.y = f2tf(a * e4[4].y + gt * s.y);
                o4.z = f2tf(a * e4[4].z + gt * s.z);
                o4.w = f2tf(a * e4[4].w + gt * s.w);
                rowp4u[128 + lane] = o4;
            }
        }
    }

    // ---------------- Phase D: out = W @ V via MMA --------------------------
    float accD[2][4] = {};
    for (int tile = 0; tile < 9; tile++) {
        const int m0 = tile * 64;
        __syncthreads();
        *(uint4*)&sKV[(lr0     ) * SV_ST + ld4] = f2tf4(pre0);
        *(uint4*)&sKV[(lr0 + 32) * SV_ST + ld4] = f2tf4(pre1);
        if (tile < 8) {
            const float* Vn = Vp + (m0 + 64) * D_;
            pre0 = *(const float4*)&Vn[(lr0     ) * D_ + ld4];
            pre1 = *(const float4*)&Vn[(lr0 + 32) * D_ + ld4];
        }
        __syncthreads();

        #pragma unroll
        for (int ks = 0; ks < 8; ks++) {
            int k0 = m0 + ks * 8;
            u32 a[4];
            a[0] = sSw[(roff + g    ) * SS_ST + k0 + tq    ];
            a[1] = sSw[(roff + g + 8) * SS_ST + k0 + tq    ];
            a[2] = sSw[(roff + g    ) * SS_ST + k0 + tq + 4];
            a[3] = sSw[(roff + g + 8) * SS_ST + k0 + tq + 4];
            #pragma unroll
            for (int nt = 0; nt < 2; nt++) {
                int nb = cg + nt * 8;
                u32 bfr[2];
                bfr[0] = sKV[(ks * 8 + tq    ) * SV_ST + nb + g];
                bfr[1] = sKV[(ks * 8 + tq + 4) * SV_ST + nb + g];
                mma_tf32(accD[nt], a, bfr);
            }
        }
    }

    float* Op = g_AO + ((size_t)(b * N_ + n0)) * C_ + h * D_;
    #pragma unroll
    for (int nt = 0; nt < 2; nt++) {
        int c0 = cg + nt * 8 + 2 * tq;
        float2 v0; v0.x = accD[nt][0]; v0.y = accD[nt][1];
        float2 v1; v1.x = accD[nt][2]; v1.y = accD[nt][3];
        *(float2*)&Op[(roff + g    ) * C_ + c0] = v0;
        *(float2*)&Op[(roff + g + 8) * C_ + c0] = v1;
    }
}

// ===========================================================================
extern "C" void kernel_launch(void* const* d_in, const int* in_sizes, int n_in,
                              void* d_out, int out_size)
{
    const float* x      = (const float*)d_in[0];
    const float* Wq     = (const float*)d_in[1];
    const float* Wk     = (const float*)d_in[2];
    const float* Wv     = (const float*)d_in[3];
    const float* Wproj  = (const float*)d_in[4];
    const float* bproj  = (const float*)d_in[5];
    const float* pos_w  = (const float*)d_in[6];
    const float* pos_b  = (const float*)d_in[7];
    const float* gating = (const float*)d_in[8];
    float* out = (float*)d_out;

    const size_t attn_smem = ATTN_SMEM_WORDS * sizeof(u32);   // ~184 KB
    cudaFuncSetAttribute(attn_kernel, cudaFuncAttributeMaxDynamicSharedMemorySize,
                         (int)attn_smem);
    cudaFuncSetAttribute(qkv_mma_kernel, cudaFuncAttributeMaxDynamicSharedMemorySize,
                         GEMM_SMEM_BYTES);
    cudaFuncSetAttribute(proj_mma_kernel, cudaFuncAttributeMaxDynamicSharedMemorySize,
                         GEMM_SMEM_BYTES);

    qkv_mma_kernel<<<dim3(B_ * N_ / 128, C_ / 128, 3), 256, GEMM_SMEM_BYTES>>>(x, Wq, Wk, Wv);
    pos_kernel<<<(H_ * N_) / 8, 256>>>(pos_w, pos_b);
    attn_kernel<<<dim3(N_ / AROWS, H_, B_), ATHREADS, attn_smem>>>(gating);
    proj_mma_kernel<<<dim3(B_ * N_ / 128, C_ / 128), 256, GEMM_SMEM_BYTES>>>(Wproj, bproj, out);
}

// round 16
// speedup vs baseline: 1.0139x; 1.0139x over previous
#include <cuda_runtime.h>

typedef unsigned int u32;

// Problem constants (fixed by the dataset)
#define B_  16
#define H_  12
#define N_  576
#define D_  64
#define C_  768
#define GW_ 24

// ---- scratch ----
__device__ float g_Q [B_*H_*N_*D_];
__device__ float g_K [B_*H_*N_*D_];
__device__ float g_V [B_*H_*N_*D_];
__device__ float g_AO[B_*N_*C_];
__device__ float g_SP[H_*N_*N_];      // positional softmax table (L2-resident, 15.9MB)

// ---------------------------------------------------------------------------
// TF32 helpers
// ---------------------------------------------------------------------------
__device__ __forceinline__ u32 f2tf(float f) {
    u32 u;
    asm("cvt.rna.tf32.f32 %0, %1;" : "=r"(u) : "f"(f));
    return u;
}
// Fragment mapping (m16n8k8, verified):
//   A: a0=(m=g,k=tq) a1=(m=g+8,k=tq) a2=(m=g,k=tq+4) a3=(m=g+8,k=tq+4)
//   B: b0=(k=tq,n=g) b1=(k=tq+4,n=g)
//   C: c0=(m=g,n=2tq) c1=(g,2tq+1) c2=(g+8,2tq) c3=(g+8,2tq+1)
__device__ __forceinline__ void mma_tf32(float* d, const u32* a, const u32* b) {
    asm volatile(
        "mma.sync.aligned.m16n8k8.row.col.f32.tf32.tf32.f32 "
        "{%0,%1,%2,%3}, {%4,%5,%6,%7}, {%8,%9}, {%0,%1,%2,%3};"
        : "+f"(d[0]), "+f"(d[1]), "+f"(d[2]), "+f"(d[3])
        : "r"(a[0]), "r"(a[1]), "r"(a[2]), "r"(a[3]), "r"(b[0]), "r"(b[1]));
}

__device__ __forceinline__ uint4 f2tf4(float4 v) {
    uint4 u; u.x = f2tf(v.x); u.y = f2tf(v.y); u.z = f2tf(v.z); u.w = f2tf(v.w);
    return u;
}

// ===========================================================================
// TF32 GEMM core (exact R12 best-measured config): 128x128 tile, BK=16,
// 4 warps x (64x64) warp tiles, double-buffered smem, CVT on the store path.
// Conflict-free layouts: sA [m][68] (banks 4g+tq=lane), sB [k][136] (8tq+g).
// ===========================================================================
#define SA_ST 68
#define SB_ST 136
#define A_WORDS (128 * SA_ST)
#define BUF_WORDS (A_WORDS + 16 * SB_ST)
#define GEMM_SMEM_BYTES (2 * BUF_WORDS * 4)

#define EPI_QKV  0
#define EPI_PROJ 1

template<int EPI>
__device__ __forceinline__ void gemm_tf32_body(
    const float* __restrict__ A, const float* __restrict__ Wm,
    int row0, int col0,
    float* __restrict__ dst, const float* __restrict__ bias)
{
    extern __shared__ __align__(16) u32 dynsm[];

    const int t    = threadIdx.x;        // 0..127
    const int w    = t >> 5;             // 0..3
    const int lane = t & 31;
    const int g    = lane >> 2;
    const int tq   = lane & 3;
    const int m0w  = (w & 1) * 64;
    const int n0w  = (w >> 1) * 64;

    const int ar = t >> 2;               // rows ar + 32*j
    const int ak = (t & 3) * 4;
    const int bk = t >> 5;               // k rows bk + 4*j
    const int bn = (t & 31) * 4;

    float acc[4][8][4] = {};
    float4 ra[4], rb[4];

    #pragma unroll
    for (int j = 0; j < 4; j++) {
        ra[j] = *(const float4*)&A [(row0 + ar + 32 * j) * C_ + ak];
        rb[j] = *(const float4*)&Wm[(bk + 4 * j) * C_ + col0 + bn];
    }
    {
        u32* sA = dynsm;
        u32* sB = dynsm + A_WORDS;
        #pragma unroll
        for (int j = 0; j < 4; j++) {
            *(uint4*)&sA[(ar + 32 * j) * SA_ST + ak] = f2tf4(ra[j]);
            *(uint4*)&sB[(bk + 4 * j ) * SB_ST + bn] = f2tf4(rb[j]);
        }
    }
    #pragma unroll
    for (int j = 0; j < 4; j++) {
        ra[j] = *(const float4*)&A [(row0 + ar + 32 * j) * C_ + 16 + ak];
        rb[j] = *(const float4*)&Wm[(16 + bk + 4 * j) * C_ + col0 + bn];
    }
    __syncthreads();

    const int NIT = C_ / 16;
    for (int it = 0; it < NIT; it++) {
        const u32* sA = dynsm + (it & 1) * BUF_WORDS;
        const u32* sB = sA + A_WORDS;

        #pragma unroll
        for (int ks = 0; ks < 16; ks += 8) {
            u32 af[4][4], bf[8][2];
            #pragma unroll
            for (int mb = 0; mb < 4; mb++) {
                int mrow = m0w + mb * 16 + g;
                af[mb][0] = sA[(mrow    ) * SA_ST + ks + tq    ];
                af[mb][1] = sA[(mrow + 8) * SA_ST + ks + tq    ];
                af[mb][2] = sA[(mrow    ) * SA_ST + ks + tq + 4];
                af[mb][3] = sA[(mrow + 8) * SA_ST + ks + tq + 4];
            }
            #pragma unroll
            for (int nb = 0; nb < 8; nb++) {
                int nc = n0w + nb * 8 + g;
                bf[nb][0] = sB[(ks + tq    ) * SB_ST + nc];
                bf[nb][1] = sB[(ks + tq + 4) * SB_ST + nc];
            }
            #pragma unroll
            for (int mb = 0; mb < 4; mb++)
                #pragma unroll
                for (int nb = 0; nb < 8; nb++)
                    mma_tf32(acc[mb][nb], af[mb], bf[nb]);
        }

        if (it + 1 < NIT) {
            u32* nA = dynsm + ((it + 1) & 1) * BUF_WORDS;
            u32* nB = nA + A_WORDS;
            #pragma unroll
            for (int j = 0; j < 4; j++) {
                *(uint4*)&nA[(ar + 32 * j) * SA_ST + ak] = f2tf4(ra[j]);
                *(uint4*)&nB[(bk + 4 * j ) * SB_ST + bn] = f2tf4(rb[j]);
            }
            if (it + 2 < NIT) {
                int k0 = (it + 2) * 16;
                #pragma unroll
                for (int j = 0; j < 4; j++) {
                    ra[j] = *(const float4*)&A [(row0 + ar + 32 * j) * C_ + k0 + ak];
                    rb[j] = *(const float4*)&Wm[(k0 + bk + 4 * j) * C_ + col0 + bn];
                }
            }
        }
        __syncthreads();
    }

    #pragma unroll
    for (int mb = 0; mb < 4; mb++) {
        int r0 = row0 + m0w + mb * 16 + g;
        #pragma unroll
        for (int nb = 0; nb < 8; nb++) {
            int c0 = col0 + n0w + nb * 8 + 2 * tq;
            #pragma unroll
            for (int rr = 0; rr < 2; rr++) {
                int row = r0 + rr * 8;
                float2 v;
                v.x = acc[mb][nb][rr * 2 + 0];
                v.y = acc[mb][nb][rr * 2 + 1];
                if (EPI == EPI_QKV) {
                    int b  = row / N_;
                    int n  = row - b * N_;
                    int hh = c0 >> 6;
                    int dd = c0 & 63;
                    *(float2*)&dst[(((b * H_ + hh) * N_) + n) * D_ + dd] = v;
                } else {
                    v.x += bias[c0];
                    v.y += bias[c0 + 1];
                    *(float2*)&dst[(size_t)row * C_ + c0] = v;
                }
            }
        }
    }
}

__global__ __launch_bounds__(128, 2) void qkv_mma_kernel(
    const float* __restrict__ x,
    const float* __restrict__ Wq,
    const float* __restrict__ Wk,
    const float* __restrict__ Wv)
{
    const float* W   = (blockIdx.z == 0) ? Wq : (blockIdx.z == 1) ? Wk : Wv;
    float*       dst = (blockIdx.z == 0) ? g_Q : (blockIdx.z == 1) ? g_K : g_V;
    gemm_tf32_body<EPI_QKV>(x, W, blockIdx.x * 128, blockIdx.y * 128, dst, 0);
}

__global__ __launch_bounds__(128, 2) void proj_mma_kernel(
    const float* __restrict__ Wproj,
    const float* __restrict__ bproj,
    float* __restrict__ out)
{
    gemm_tf32_body<EPI_PROJ>(g_AO, Wproj, blockIdx.x * 128, blockIdx.y * 128,
                             out, bproj);
}

// ===========================================================================
// K2: positional softmax table S_pos[h][n][m]. One warp per (h,n) row.
// ===========================================================================
__global__ __launch_bounds__(256) void pos_kernel(
    const float* __restrict__ pos_w,
    const float* __restrict__ pos_b)
{
    const int warp = threadIdx.x >> 5;
    const int lane = threadIdx.x & 31;
    const int row  = blockIdx.x * 8 + warp;
    const int h    = row / N_;
    const int n    = row - h * N_;

    const float wx = pos_w[0 * H_ + h];
    const float wy = pos_w[1 * H_ + h];
    const float wz = pos_w[2 * H_ + h];
    const float pb = pos_b[h];
    const int nx = n % GW_, ny = n / GW_;

    float buf[18];
    float mx = -1e30f;
    #pragma unroll
    for (int i = 0; i < 18; i++) {
        int m  = lane + 32 * i;
        float fdx = (float)((m % GW_) - nx);
        float fdy = (float)((m / GW_) - ny);
        float s = wx * fdx + wy * fdy + wz * (fdx * fdx + fdy * fdy) + pb;
        buf[i] = s;
        mx = fmaxf(mx, s);
    }
    #pragma unroll
    for (int o = 16; o; o >>= 1) mx = fmaxf(mx, __shfl_xor_sync(0xffffffffu, mx, o));

    float sum = 0.f;
    #pragma unroll
    for (int i = 0; i < 18; i++) { buf[i] = __expf(buf[i] - mx); sum += buf[i]; }
    #pragma unroll
    for (int o = 16; o; o >>= 1) sum += __shfl_xor_sync(0xffffffffu, sum, o);

    const float inv = 1.f / sum;
    float* dstp = g_SP + (size_t)row * N_;
    #pragma unroll
    for (int i = 0; i < 18; i++) dstp[lane + 32 * i] = buf[i] * inv;
}

// ===========================================================================
// K3: fused attention, TF32 MMA, 64 query rows per block (512 threads).
// K/V tiles of 192 rows (3 tiles per phase instead of 9): barrier count per
// phase drops 18 -> 6 and each STS burst amortizes 3x the MMA work.
// Bank-verified: sQ/sK stride 68 (banks 4g+tq), sV stride 72 (8tq+g),
// sS stride 580 (4g+tq). m-accumulation order unchanged -> bit-identical.
// ===========================================================================
#define SQ_ST 68
#define SK_ST 68
#define SV_ST 72
#define SS_ST 580
#define AROWS 64
#define KT    192
#define NKT   3          // 576 / 192
#define ATHREADS 512
#define ATTN_SMEM_WORDS (AROWS*SQ_ST + KT*SV_ST + AROWS*SS_ST)   // 55296 (~221 KB)

__global__ __launch_bounds__(ATHREADS, 1) void attn_kernel(const float* __restrict__ gating)
{
    extern __shared__ __align__(16) u32 smw[];
    u32*   sQ   = smw;                           // tf32 [64][SQ_ST]
    u32*   sKV  = sQ + AROWS * SQ_ST;            // tf32 K [192][68] / V [192][72]
    float* sS   = (float*)(sKV + KT * SV_ST);    // fp32 scores -> tf32 weights [64][SS_ST]
    u32*   sSw  = (u32*)sS;

    const int b  = blockIdx.z;
    const int h  = blockIdx.y;
    const int n0 = blockIdx.x * AROWS;
    const int t  = threadIdx.x;
    const int w    = t >> 5;
    const int lane = t & 31;
    const int g    = lane >> 2;
    const int tq   = lane & 3;
    const int roff = (w & 3) * 16;     // row group: 0,16,32,48
    const int cg   = (w >> 2) * 16;    // col group within 64

    const float* Qp = g_Q + (((size_t)(b * H_ + h)) * N_ + n0) * D_;
    const float* Kp = g_K + ((size_t)(b * H_ + h)) * N_ * D_;
    const float* Vp = g_V + ((size_t)(b * H_ + h)) * N_ * D_;

    // tile loader: 192x64 tile = 3072 float4, 6 per thread; chunk j covers
    // rows 32j..32j+31 (row = (t+512j)>>4, d4 = (t&15)<<2)
    const int lr  = t >> 4;            // 0..31 within chunk
    const int ld4 = (t & 15) << 2;

    // load Q tile (64 rows, 2 chunks)
    *(uint4*)&sQ[(lr     ) * SQ_ST + ld4] = f2tf4(*(const float4*)&Qp[(lr     ) * D_ + ld4]);
    *(uint4*)&sQ[(lr + 32) * SQ_ST + ld4] = f2tf4(*(const float4*)&Qp[(lr + 32) * D_ + ld4]);
    __syncthreads();

    // hoist Q fragments (invariant across K tiles)
    u32 qf[8][4];
    #pragma unroll
    for (int ks = 0; ks < 8; ks++) {
        int k0 = ks * 8;
        qf[ks][0] = sQ[(roff + g    ) * SQ_ST + k0 + tq    ];
        qf[ks][1] = sQ[(roff + g + 8) * SQ_ST + k0 + tq    ];
        qf[ks][2] = sQ[(roff + g    ) * SQ_ST + k0 + tq + 4];
        qf[ks][3] = sQ[(roff + g + 8) * SQ_ST + k0 + tq + 4];
    }

    // ---------------- Phase A: scores via MMA, 192-row K tiles -------------
    float4 pre[6];
    #pragma unroll
    for (int j = 0; j < 6; j++)
        pre[j] = *(const float4*)&Kp[(lr + 32 * j) * D_ + ld4];

    for (int tile = 0; tile < NKT; tile++) {
        const int m0 = tile * KT;
        __syncthreads();                       // prev tile's MMAs done
        #pragma unroll
        for (int j = 0; j < 6; j++)
            *(uint4*)&sKV[(lr + 32 * j) * SK_ST + ld4] = f2tf4(pre[j]);
        if (tile + 1 < NKT) {
            const float* Kn = Kp + (m0 + KT) * D_;
            #pragma unroll
            for (int j = 0; j < 6; j++)
                pre[j] = *(const float4*)&Kn[(lr + 32 * j) * D_ + ld4];
        }
        __syncthreads();

        #pragma unroll
        for (int seg = 0; seg < 3; seg++) {    // 64-col segments within tile
            float acc[2][4] = {};
            #pragma unroll
            for (int ks = 0; ks < 8; ks++) {
                int k0 = ks * 8;
                #pragma unroll
                for (int nt = 0; nt < 2; nt++) {
                    int nb = seg * 64 + cg + nt * 8;
                    u32 bfr[2];
                    bfr[0] = sKV[(nb + g) * SK_ST + k0 + tq    ];
                    bfr[1] = sKV[(nb + g) * SK_ST + k0 + tq + 4];
                    mma_tf32(acc[nt], qf[ks], bfr);
                }
            }
            #pragma unroll
            for (int nt = 0; nt < 2; nt++) {
                int c0 = m0 + seg * 64 + cg + nt * 8 + 2 * tq;
                float2 v0; v0.x = acc[nt][0] * 0.125f; v0.y = acc[nt][1] * 0.125f;
                float2 v1; v1.x = acc[nt][2] * 0.125f; v1.y = acc[nt][3] * 0.125f;
                *(float2*)&sS[(roff + g    ) * SS_ST + c0] = v0;
                *(float2*)&sS[(roff + g + 8) * SS_ST + c0] = v1;
            }
        }
    }

    // prefetch V tile 0 — overlaps with softmax/blend below
    #pragma unroll
    for (int j = 0; j < 6; j++)
        pre[j] = *(const float4*)&Vp[(lr + 32 * j) * D_ + ld4];

    __syncthreads();                           // all scores written

    // ---------------- Merged softmax + positional blend (tf32 out) ---------
    {
        const float gt = 1.f / (1.f + __expf(-gating[h]));
        const float c1 = 1.f - gt;
        const bool  tail = (lane < 16);

        for (int r = w; r < AROWS; r += 16) {
            float4* rowp4 = (float4*)(sS + r * SS_ST);
            uint4*  rowp4u = (uint4*)rowp4;
            float4 e4[5];
            float mx = -1e30f;
            #pragma unroll
            for (int i = 0; i < 4; i++) {
                e4[i] = rowp4[lane + 32 * i];
                mx = fmaxf(mx, fmaxf(fmaxf(e4[i].x, e4[i].y), fmaxf(e4[i].z, e4[i].w)));
            }
            if (tail) {
                e4[4] = rowp4[128 + lane];
                mx = fmaxf(mx, fmaxf(fmaxf(e4[4].x, e4[4].y), fmaxf(e4[4].z, e4[4].w)));
            } else {
                e4[4].x = e4[4].y = e4[4].z = e4[4].w = -1e30f;
            }
            #pragma unroll
            for (int o = 16; o; o >>= 1) mx = fmaxf(mx, __shfl_xor_sync(0xffffffffu, mx, o));

            float sum = 0.f;
            #pragma unroll
            for (int i = 0; i < 5; i++) {
                e4[i].x = __expf(e4[i].x - mx);
                e4[i].y = __expf(e4[i].y - mx);
                e4[i].z = __expf(e4[i].z - mx);
                e4[i].w = __expf(e4[i].w - mx);
                sum += (e4[i].x + e4[i].y) + (e4[i].z + e4[i].w);
            }
            #pragma unroll
            for (int o = 16; o; o >>= 1) sum += __shfl_xor_sync(0xffffffffu, sum, o);
            const float a = c1 / sum;

            const float4* sp4 = (const float4*)(g_SP + ((size_t)h * N_ + n0 + r) * N_);
            #pragma unroll
            for (int i = 0; i < 4; i++) {
                float4 s = sp4[lane + 32 * i];
                uint4 o4;
                o4.x = f2tf(a * e4[i].x + gt * s.x);
                o4.y = f2tf(a * e4[i].y + gt * s.y);
                o4.z = f2tf(a * e4[i].z + gt * s.z);
                o4.w = f2tf(a * e4[i].w + gt * s.w);
                rowp4u[lane + 32 * i] = o4;
            }
            if (tail) {
                float4 s = sp4[128 + lane];
                uint4 o4;
                o4.x = f2tf(a * e4[4].x + gt * s.x);
                o4.y = f2tf(a * e4[4].y + gt * s.y);
                o4.z = f2tf(a * e4[4].z + gt * s.z);
                o4.w = f2tf(a * e4[4].w + gt * s.w);
                rowp4u[128 + lane] = o4;
            }
        }
    }

    // ---------------- Phase D: out = W @ V via MMA, 192-row V tiles ---------
    float accD[2][4] = {};
    for (int tile = 0; tile < NKT; tile++) {
        const int m0 = tile * KT;
        __syncthreads();                 // blend done (tile 0) / prev MMAs done
        #pragma unroll
        for (int j = 0; j < 6; j++)
            *(uint4*)&sKV[(lr + 32 * j) * SV_ST + ld4] = f2tf4(pre[j]);
        if (tile + 1 < NKT) {
            const float* Vn = Vp + (m0 + KT) * D_;
            #pragma unroll
            for (int j = 0; j < 6; j++)
                pre[j] = *(const float4*)&Vn[(lr + 32 * j) * D_ + ld4];
        }
        __syncthreads();

        #pragma unroll
        for (int seg = 0; seg < 3; seg++) {
            #pragma unroll
            for (int ks = 0; ks < 8; ks++) {
                int kl  = seg * 64 + ks * 8;       // local k within V tile
                int k0g = m0 + kl;                  // global k for weights
                u32 a[4];
                a[0] = sSw[(roff + g    ) * SS_ST + k0g + tq    ];
                a[1] = sSw[(roff + g + 8) * SS_ST + k0g + tq    ];
                a[2] = sSw[(roff + g    ) * SS_ST + k0g + tq + 4];
                a[3] = sSw[(roff + g + 8) * SS_ST + k0g + tq + 4];
                #pragma unroll
                for (int nt = 0; nt < 2; nt++) {
                    int nb = cg + nt * 8;
                    u32 bfr[2];
                    bfr[0] = sKV[(kl + tq    ) * SV_ST + nb + g];
                    bfr[1] = sKV[(kl + tq + 4) * SV_ST + nb + g];
                    mma_tf32(accD[nt], a, bfr);
                }
            }
        }
    }

    float* Op = g_AO + ((size_t)(b * N_ + n0)) * C_ + h * D_;
    #pragma unroll
    for (int nt = 0; nt < 2; nt++) {
        int c0 = cg + nt * 8 + 2 * tq;
        float2 v0; v0.x = accD[nt][0]; v0.y = accD[nt][1];
        float2 v1; v1.x = accD[nt][2]; v1.y = accD[nt][3];
        *(float2*)&Op[(roff + g    ) * C_ + c0] = v0;
        *(float2*)&Op[(roff + g + 8) * C_ + c0] = v1;
    }
}

// ===========================================================================
extern "C" void kernel_launch(void* const* d_in, const int* in_sizes, int n_in,
                              void* d_out, int out_size)
{
    const float* x      = (const float*)d_in[0];
    const float* Wq     = (const float*)d_in[1];
    const float* Wk     = (const float*)d_in[2];
    const float* Wv     = (const float*)d_in[3];
    const float* Wproj  = (const float*)d_in[4];
    const float* bproj  = (const float*)d_in[5];
    const float* pos_w  = (const float*)d_in[6];
    const float* pos_b  = (const float*)d_in[7];
    const float* gating = (const float*)d_in[8];
    float* out = (float*)d_out;

    const size_t attn_smem = ATTN_SMEM_WORDS * sizeof(u32);   // ~221 KB
    cudaFuncSetAttribute(attn_kernel, cudaFuncAttributeMaxDynamicSharedMemorySize,
                         (int)attn_smem);
    cudaFuncSetAttribute(qkv_mma_kernel, cudaFuncAttributeMaxDynamicSharedMemorySize,
                         GEMM_SMEM_BYTES);
    cudaFuncSetAttribute(proj_mma_kernel, cudaFuncAttributeMaxDynamicSharedMemorySize,
                         GEMM_SMEM_BYTES);

    qkv_mma_kernel<<<dim3(B_ * N_ / 128, C_ / 128, 3), 128, GEMM_SMEM_BYTES>>>(x, Wq, Wk, Wv);
    pos_kernel<<<(H_ * N_) / 8, 256>>>(pos_w, pos_b);
    attn_kernel<<<dim3(N_ / AROWS, H_, B_), ATHREADS, attn_smem>>>(gating);
    proj_mma_kernel<<<dim3(B_ * N_ / 128, C_ / 128), 128, GEMM_SMEM_BYTES>>>(Wproj, bproj, out);
}